// round 1
// baseline (speedup 1.0000x reference)
#include <cuda_runtime.h>
#include <cuda_bf16.h>

// Problem constants (fixed by the reference)
#define BB      16
#define SS      512
#define NH      8
#define M_BLOOM 4096
#define WW      2
#define KBLK    (2 * WW + 1)   // 5

// ---------------------------------------------------------------------------
// Kernel 1: stream 671 MB of zeros to the output at write-bandwidth peak.
// Grid-stride over float4 (16B) stores; write-only, perfectly coalesced.
// ---------------------------------------------------------------------------
__global__ void __launch_bounds__(256) bloom_zero_kernel(float4* __restrict__ out,
                                                         long long n4) {
    long long i      = (long long)blockIdx.x * blockDim.x + threadIdx.x;
    long long stride = (long long)gridDim.x * blockDim.x;
    const float4 z = make_float4(0.f, 0.f, 0.f, 0.f);
    // Unroll-by-4 grid-stride loop: 4 independent STG.128 in flight per thread.
    long long i3_limit = n4 - 3 * stride;
    for (; i < i3_limit; i += 4 * stride) {
        out[i]              = z;
        out[i + stride]     = z;
        out[i + 2 * stride] = z;
        out[i + 3 * stride] = z;
    }
    for (; i < n4; i += stride) {
        out[i] = z;
    }
}

// ---------------------------------------------------------------------------
// Kernel 2: scatter the <=327,680 increments.
// One thread per (b, s, n) hash; each contributes +1 at 5 shifted positions:
//   out[b, k*M + (h % M), s + (W - k)]   for k = 0..4, when j in [0, S).
// Output layout: out[((b*KBLK + k)*M_BLOOM + m)*SS + j]
// ---------------------------------------------------------------------------
__global__ void __launch_bounds__(256) bloom_scatter_kernel(const int* __restrict__ hashes,
                                                            float* __restrict__ out) {
    int idx = blockIdx.x * blockDim.x + threadIdx.x;
    if (idx >= BB * SS * NH) return;

    int s = (idx / NH) % SS;
    int b = idx / (NH * SS);
    int fp = hashes[idx] & (M_BLOOM - 1);   // hashes >= 0, M is a power of 2

    long long base = ((long long)b * KBLK) * M_BLOOM + fp;  // row index for k=0
#pragma unroll
    for (int k = 0; k < KBLK; k++) {
        int j = s + (WW - k);
        if (j >= 0 && j < SS) {
            long long o = (base + (long long)k * M_BLOOM) * SS + j;
            atomicAdd(&out[o], 1.0f);
        }
    }
}

extern "C" void kernel_launch(void* const* d_in, const int* in_sizes, int n_in,
                              void* d_out, int out_size) {
    const int* hashes = (const int*)d_in[0];
    float* out = (float*)d_out;

    // out_size = 16 * 20480 * 512 = 167,772,160 floats, divisible by 4.
    long long n4 = (long long)out_size / 4;

    // ~4736 CTAs = 148 SMs * 32; each thread does ~34 float4 stores.
    bloom_zero_kernel<<<4736, 256>>>((float4*)out, n4);

    int n_hash = BB * SS * NH;  // 65536
    bloom_scatter_kernel<<<(n_hash + 255) / 256, 256>>>(hashes, out);
}